// round 1
// baseline (speedup 1.0000x reference)
#include <cuda_runtime.h>
#include <math.h>

#define T_SEQ   4096
#define NNODES  64
#define FPL     8
#define OBS_DIM 512
#define HID     64
#define GATES   256

// scratch: hs[t][n][k]  (64 MB, static device allocation — allowed)
__device__ float g_hs[T_SEQ * NNODES * HID];

__device__ __forceinline__ float sigm(float x) {
    return 1.0f / (1.0f + expf(-x));
}

// ---------------------------------------------------------------------------
// Kernel 1: 64 independent LSTMs (one CTA per node), T=4096 recurrent steps.
// Thread g (0..255) owns gate-row g: W_hh[g,:] (64 regs) + W_ih[g,:] (8 regs).
// h lives in smem (broadcast reads), c lives in registers of threads 0..63.
// ---------------------------------------------------------------------------
__global__ void __launch_bounds__(256, 1)
lstm_kernel(const float* __restrict__ x,
            const float* __restrict__ W_ih,
            const float* __restrict__ W_hh,
            const float* __restrict__ b_ih,
            const float* __restrict__ b_hh,
            float* __restrict__ out)   // for hn/cn tail
{
    const int n = blockIdx.x;     // node id
    const int g = threadIdx.x;    // gate row 0..255

    __shared__ __align__(16) float h_s[HID];
    __shared__ float gates_s[GATES];
    __shared__ float xb[FPL];

    // Per-thread weights in registers
    float wih[FPL];
#pragma unroll
    for (int j = 0; j < FPL; j++) wih[j] = W_ih[g * FPL + j];
    float whh[HID];
#pragma unroll
    for (int k = 0; k < HID; k++) whh[k] = W_hh[g * HID + k];
    const float bsum = b_ih[g] + b_hh[g];

    float c_reg = 0.0f;
    if (g < HID) h_s[g] = 0.0f;

    const float* xrow = x + n * FPL;   // x[t, n*8 + j] = xrow[t*OBS_DIM + j]

    for (int t = 0; t < T_SEQ; t++) {
        // stage x[t] for this node
        if (g < FPL) xb[g] = xrow[t * OBS_DIM + g];
        __syncthreads();   // h_s(t-1), xb(t) visible

        // gates[g] = bsum + W_ih[g,:]·x + W_hh[g,:]·h
        float acc = bsum;
#pragma unroll
        for (int j = 0; j < FPL; j++) acc += wih[j] * xb[j];
        const float4* h4 = (const float4*)h_s;
#pragma unroll
        for (int k4 = 0; k4 < HID / 4; k4++) {
            float4 hv = h4[k4];
            acc += whh[4 * k4 + 0] * hv.x;
            acc += whh[4 * k4 + 1] * hv.y;
            acc += whh[4 * k4 + 2] * hv.z;
            acc += whh[4 * k4 + 3] * hv.w;
        }
        gates_s[g] = acc;
        __syncthreads();   // all gates written

        // update h, c (threads 0..63), gate order i, f, g, o
        if (g < HID) {
            float ig = sigm(gates_s[g]);
            float fg = sigm(gates_s[HID + g]);
            float gg = tanhf(gates_s[2 * HID + g]);
            float og = sigm(gates_s[3 * HID + g]);
            c_reg = fg * c_reg + ig * gg;
            float h = og * tanhf(c_reg);
            h_s[g] = h;
            g_hs[(t * NNODES + n) * HID + g] = h;
        }
        // next iteration's first __syncthreads orders h_s for the gate GEMV
    }

    // final state outputs: hn at offset 2*T*64, cn after it
    if (g < HID) {
        const int base = 2 * T_SEQ * NNODES;
        out[base + n * HID + g] = h_s[g];
        out[base + NNODES * HID + n * HID + g] = c_reg;
    }
}

// ---------------------------------------------------------------------------
// Kernel 2: per-timestep head. GAT collapses to identity-attention, so:
//   hbar = mean_n hs[t,n,:]; gvec = relu(W_gat@hbar + b_gat);
//   mean = W_mean@gvec + b_mean; std = clip(softplus(W_std@gvec + b_std),...)
// One CTA per timestep.
// ---------------------------------------------------------------------------
__global__ void __launch_bounds__(256, 4)
head_kernel(const float* __restrict__ W_gat,
            const float* __restrict__ b_gat,
            const float* __restrict__ W_mean,
            const float* __restrict__ b_mean,
            const float* __restrict__ W_std,
            const float* __restrict__ b_std,
            float* __restrict__ out)
{
    const int t = blockIdx.x;
    const int tid = threadIdx.x;

    __shared__ __align__(16) float hsb[NNODES * HID];   // 16 KB
    __shared__ float partials[256];
    __shared__ float hbar[HID];
    __shared__ float gsh[GATES];

    // coalesced load of hs[t] tile
    const float* src = g_hs + t * NNODES * HID;
    const float4* src4 = (const float4*)src;
    float4* dst4 = (float4*)hsb;
#pragma unroll
    for (int i = tid; i < NNODES * HID / 4; i += 256) dst4[i] = src4[i];
    __syncthreads();

    // mean over nodes: thread (part,k) sums 16 nodes
    {
        const int k = tid & 63, part = tid >> 6;
        float s = 0.0f;
#pragma unroll
        for (int m = 0; m < 16; m++) s += hsb[(part * 16 + m) * HID + k];
        partials[part * 64 + k] = s;
    }
    __syncthreads();
    if (tid < HID) {
        hbar[tid] = (partials[tid] + partials[64 + tid] +
                     partials[128 + tid] + partials[192 + tid]) * (1.0f / 64.0f);
    }
    __syncthreads();

    // gvec[tid] = relu(W_gat[tid,:]·hbar + b_gat[tid])
    {
        float acc = b_gat[tid];
        const float* wr = W_gat + tid * HID;
#pragma unroll
        for (int k = 0; k < HID; k++) acc += wr[k] * hbar[k];
        gsh[tid] = fmaxf(acc, 0.0f);
    }
    __syncthreads();

    // action heads
    if (tid < 128) {
        const int  a      = tid & 63;
        const bool is_std = (tid >= 64);
        const float* W = is_std ? W_std : W_mean;
        float acc = is_std ? b_std[a] : b_mean[a];
        const float* wr = W + a * GATES;
#pragma unroll 8
        for (int j = 0; j < GATES; j++) acc += wr[j] * gsh[j];
        if (is_std) {
            float sp = (acc > 20.0f) ? acc : log1pf(expf(acc));
            sp = fminf(fmaxf(sp, 0.001f), 10.0f);
            out[T_SEQ * NNODES + t * NNODES + a] = sp;
        } else {
            out[t * NNODES + a] = acc;
        }
    }
}

// ---------------------------------------------------------------------------
// launch
// ---------------------------------------------------------------------------
extern "C" void kernel_launch(void* const* d_in, const int* in_sizes, int n_in,
                              void* d_out, int out_size)
{
    const float* x      = (const float*)d_in[0];
    const float* W_ih   = (const float*)d_in[1];
    const float* W_hh   = (const float*)d_in[2];
    const float* b_ih   = (const float*)d_in[3];
    const float* b_hh   = (const float*)d_in[4];
    const float* W_gat  = (const float*)d_in[5];
    // d_in[6] = att_src, d_in[7] = att_dst : provably unused (identity adjacency
    // -> softmax over a single element == 1 regardless of attention logits)
    const float* b_gat  = (const float*)d_in[8];
    const float* W_mean = (const float*)d_in[9];
    const float* b_mean = (const float*)d_in[10];
    const float* W_std  = (const float*)d_in[11];
    const float* b_std  = (const float*)d_in[12];
    float* out = (float*)d_out;

    lstm_kernel<<<NNODES, 256>>>(x, W_ih, W_hh, b_ih, b_hh, out);
    head_kernel<<<T_SEQ, 256>>>(W_gat, b_gat, W_mean, b_mean, W_std, b_std, out);
}

// round 2
// speedup vs baseline: 1.9047x; 1.9047x over previous
#include <cuda_runtime.h>
#include <math.h>

#define T_SEQ   4096
#define NNODES  64
#define FPL     8
#define OBS_DIM 512
#define HID     64
#define GATES   256
#define FULLMASK 0xffffffffu

// scratch (static device allocations — allowed)
__device__ float g_hs[T_SEQ * NNODES * HID];          // 64 MB: h[t][n][k]
__device__ float g_Wg_t[HID * GATES];                 // W_gat transposed [k][j]
__device__ float g_Wm_t[GATES * HID];                 // W_mean transposed [j][a]
__device__ float g_Ws_t[GATES * HID];                 // W_std  transposed [j][a]

typedef unsigned long long ull;

__device__ __forceinline__ void ffma2(ull& d, const ull a, const ull b) {
    asm("fma.rn.f32x2 %0, %1, %2, %0;" : "+l"(d) : "l"(a), "l"(b));
}
__device__ __forceinline__ float2 unpack2(ull v) {
    float2 f; asm("mov.b64 {%0, %1}, %2;" : "=f"(f.x), "=f"(f.y) : "l"(v)); return f;
}
// fast, accurate-enough activations (MUFU.EX2 + MUFU.RCP, ~1e-6 rel err)
__device__ __forceinline__ float sigm_fast(float x) {
    return __fdividef(1.0f, 1.0f + __expf(-x));
}
__device__ __forceinline__ float tanh_fast(float x) {
    return 1.0f - 2.0f * __fdividef(1.0f, 1.0f + __expf(2.0f * x));
}

// ---------------------------------------------------------------------------
// Kernel 0: one-time weight transposes for coalesced head GEMVs
// ---------------------------------------------------------------------------
__global__ void transpose_kernel(const float* __restrict__ Wg,
                                 const float* __restrict__ Wm,
                                 const float* __restrict__ Ws)
{
    int i = blockIdx.x * 256 + threadIdx.x;   // grid covers 16384
    if (i < GATES * HID) {
        int j = i >> 6, k = i & 63;           // Wg[j][k]
        g_Wg_t[k * GATES + j] = Wg[i];
        int a = i >> 8, jj = i & 255;         // Wm[a][jj]
        g_Wm_t[jj * HID + a] = Wm[i];
        g_Ws_t[jj * HID + a] = Ws[i];
    }
}

// ---------------------------------------------------------------------------
// Kernel 1: 64 independent LSTMs, one CTA per node, T=4096 steps.
// Thread tid -> (k = tid>>2, gate = tid&3). Row r = gate*64 + k.
// Gate combine via warp shuffle (lanes 4k..4k+3 share k) -> 1 barrier/step.
// x prefetched 32 steps ahead (reg -> smem double buffer).
// ---------------------------------------------------------------------------
__global__ void __launch_bounds__(256, 1)
lstm_kernel(const float* __restrict__ x,
            const float* __restrict__ W_ih,
            const float* __restrict__ W_hh,
            const float* __restrict__ b_ih,
            const float* __restrict__ b_hh,
            float* __restrict__ out)
{
    const int n    = blockIdx.x;
    const int tid  = threadIdx.x;
    const int k    = tid >> 2;
    const int gate = tid & 3;
    const int r    = gate * HID + k;
    const unsigned lane = tid & 31u;
    const unsigned lb   = lane & ~3u;

    __shared__ __align__(16) float h2[2][HID];
    __shared__ __align__(16) float xs[2][32][FPL];   // 2 KB

    // weights in registers (packed as f32x2)
    ull whh[32];
    {
        const ulonglong2* wrow = (const ulonglong2*)(W_hh + r * HID);
#pragma unroll
        for (int m = 0; m < 16; m++) { ulonglong2 v = wrow[m]; whh[2*m] = v.x; whh[2*m+1] = v.y; }
    }
    ull wih[4];
    {
        const ulonglong2* wrow = (const ulonglong2*)(W_ih + r * FPL);
        ulonglong2 v0 = wrow[0], v1 = wrow[1];
        wih[0] = v0.x; wih[1] = v0.y; wih[2] = v1.x; wih[3] = v1.y;
    }
    const float bsum = b_ih[r] + b_hh[r];

    float c_reg = 0.0f;
    if (tid < HID) h2[0][tid] = 0.0f;

    // prologue: batch 0 of x
    {
        int s = tid >> 3, j = tid & 7;
        xs[0][s][j] = x[s * OBS_DIM + n * FPL + j];
    }
    __syncthreads();

    for (int b = 0; b < T_SEQ / 32; b++) {
        // prefetch next batch into a register (latency hidden over 32 steps)
        float xpref = 0.0f;
        {
            int tn = (b + 1) * 32 + (tid >> 3);
            if (tn < T_SEQ) xpref = x[tn * OBS_DIM + n * FPL + (tid & 7)];
        }
#pragma unroll 2
        for (int s = 0; s < 32; s++) {
            const int t   = b * 32 + s;
            const int par = s & 1;

            // acc = W_hh[r,:]·h + W_ih[r,:]·x  (packed f32x2, 4 accumulators)
            ull a0 = 0, a1 = 0, a2 = 0, a3 = 0;
            const ulonglong2* hp = (const ulonglong2*)h2[par];
#pragma unroll
            for (int m = 0; m < 8; m++) {
                ulonglong2 hv0 = hp[2*m], hv1 = hp[2*m+1];
                ffma2(a0, whh[4*m+0], hv0.x);
                ffma2(a1, whh[4*m+1], hv0.y);
                ffma2(a2, whh[4*m+2], hv1.x);
                ffma2(a3, whh[4*m+3], hv1.y);
            }
            {
                const ulonglong2* xp = (const ulonglong2*)xs[b & 1][s];
                ulonglong2 xv0 = xp[0], xv1 = xp[1];
                ffma2(a0, wih[0], xv0.x);
                ffma2(a1, wih[1], xv0.y);
                ffma2(a2, wih[2], xv1.x);
                ffma2(a3, wih[3], xv1.y);
            }
            float2 f0 = unpack2(a0), f1 = unpack2(a1), f2 = unpack2(a2), f3 = unpack2(a3);
            float accv = bsum + (((f0.x + f0.y) + (f1.x + f1.y)) +
                                 ((f2.x + f2.y) + (f3.x + f3.y)));

            // activation: gates i,f,o -> sigmoid; gate g -> tanh
            float v = (gate == 2) ? tanh_fast(accv) : sigm_fast(accv);

            // gather i,f,g,o within warp (lanes lb..lb+3 share k)
            float vi = __shfl_sync(FULLMASK, v, lb);
            float vf = __shfl_sync(FULLMASK, v, lb | 1);
            float vg = __shfl_sync(FULLMASK, v, lb | 2);
            float vo = __shfl_sync(FULLMASK, v, lb | 3);

            if (gate == 0) {
                c_reg = vf * c_reg + vi * vg;
                float h = vo * tanh_fast(c_reg);
                h2[par ^ 1][k] = h;
                g_hs[(t * NNODES + n) * HID + k] = h;
            }
            // stage next x batch mid-way (write-only buffer, no readers this batch)
            if (s == 20) xs[(b + 1) & 1][tid >> 3][tid & 7] = xpref;
            __syncthreads();
        }
    }

    // hn / cn
    if (gate == 0) {
        const int base = 2 * T_SEQ * NNODES;
        out[base + n * HID + k] = h2[0][k];   // t=4095 wrote parity (4095&1)^1 -> h2[0]
        out[base + NNODES * HID + n * HID + k] = c_reg;
    }
}

// ---------------------------------------------------------------------------
// Kernel 2: fused mean-pool + head. 64 CTAs x 64 timesteps each.
// GAT collapses to identity-attention + mean-pool commutes with W_gat.
// All weight loads lane-coalesced via pre-transposed matrices (L1-resident).
// ---------------------------------------------------------------------------
__global__ void __launch_bounds__(256, 1)
head_kernel(const float* __restrict__ b_gat,
            const float* __restrict__ b_mean,
            const float* __restrict__ b_std,
            float* __restrict__ out)
{
    const int t0  = blockIdx.x * 64;
    const int tid = threadIdx.x;

    __shared__ __align__(16) float hbar_s[64][HID];   // 16 KB
    __shared__ float g_s[GATES];

    // Phase A: hbar[t][k] = mean_n h[t][n][k].
    // thread (k = tid&63, q = tid>>6) handles t_local in {q, q+4, ...}
    {
        const int k = tid & 63, q = tid >> 6;
#pragma unroll
        for (int i = 0; i < 16; i++) {
            const int tl = q + 4 * i;
            const float* base = g_hs + ((long)(t0 + tl) * NNODES) * HID + k;
            float s = 0.0f;
#pragma unroll 8
            for (int nn = 0; nn < NNODES; nn++) s += base[nn * HID];
            hbar_s[tl][k] = s * (1.0f / 64.0f);
        }
    }
    __syncthreads();

    const float bg = b_gat[tid];
    for (int i = 0; i < 64; i++) {
        const int t = t0 + i;
        // g[j] = relu(W_gat[j,:]·hbar + b_gat[j])   (coalesced: Wg_t[k][j])
        {
            float acc = bg;
            const float* hb = hbar_s[i];
#pragma unroll
            for (int k = 0; k < HID; k++) acc += g_Wg_t[k * GATES + tid] * hb[k];
            g_s[tid] = fmaxf(acc, 0.0f);
        }
        __syncthreads();

        if (tid < 128) {
            const int  a      = tid & 63;
            const bool is_std = (tid >= 64);
            const float* Wt = is_std ? g_Ws_t : g_Wm_t;
            float acc = is_std ? b_std[a] : b_mean[a];
#pragma unroll 8
            for (int j = 0; j < GATES; j++) acc += Wt[j * HID + a] * g_s[j];
            if (is_std) {
                float sp = (acc > 20.0f) ? acc : log1pf(__expf(acc));
                sp = fminf(fmaxf(sp, 0.001f), 10.0f);
                out[T_SEQ * NNODES + t * NNODES + a] = sp;
            } else {
                out[t * NNODES + a] = acc;
            }
        }
        __syncthreads();   // WAR on g_s
    }
}

// ---------------------------------------------------------------------------
// launch
// ---------------------------------------------------------------------------
extern "C" void kernel_launch(void* const* d_in, const int* in_sizes, int n_in,
                              void* d_out, int out_size)
{
    const float* x      = (const float*)d_in[0];
    const float* W_ih   = (const float*)d_in[1];
    const float* W_hh   = (const float*)d_in[2];
    const float* b_ih   = (const float*)d_in[3];
    const float* b_hh   = (const float*)d_in[4];
    const float* W_gat  = (const float*)d_in[5];
    // d_in[6], d_in[7] (att_src/att_dst) provably unused: identity adjacency
    // -> softmax over a single unmasked element == 1 for any logits.
    const float* b_gat  = (const float*)d_in[8];
    const float* W_mean = (const float*)d_in[9];
    const float* b_mean = (const float*)d_in[10];
    const float* W_std  = (const float*)d_in[11];
    const float* b_std  = (const float*)d_in[12];
    float* out = (float*)d_out;

    transpose_kernel<<<64, 256>>>(W_gat, W_mean, W_std);
    lstm_kernel<<<NNODES, 256>>>(x, W_ih, W_hh, b_ih, b_hh, out);
    head_kernel<<<T_SEQ / 64, 256>>>(b_gat, b_mean, b_std, out);
}

// round 3
// speedup vs baseline: 1.9458x; 1.0216x over previous
#include <cuda_runtime.h>
#include <math.h>

#define T_SEQ   4096
#define NNODES  64
#define FPL     8
#define OBS_DIM 512
#define HID     64
#define GATES   256
#define FULLMASK 0xffffffffu

// scratch (static device allocations — allowed)
__device__ float g_hs[T_SEQ * NNODES * HID];          // 64 MB: h[t][n][k]
__device__ float g_Wg_t[HID * GATES];                 // W_gat transposed [k][j]
__device__ float g_Wm_t[GATES * HID];                 // W_mean transposed [j][a]
__device__ float g_Ws_t[GATES * HID];                 // W_std  transposed [j][a]

typedef unsigned long long ull;

__device__ __forceinline__ void ffma2(ull& d, const ull a, const ull b) {
    asm("fma.rn.f32x2 %0, %1, %2, %0;" : "+l"(d) : "l"(a), "l"(b));
}
__device__ __forceinline__ float2 unpack2(ull v) {
    float2 f; asm("mov.b64 {%0, %1}, %2;" : "=f"(f.x), "=f"(f.y) : "l"(v)); return f;
}
__device__ __forceinline__ ull pack2(float lo, float hi) {
    ull v; asm("mov.b64 %0, {%1, %2};" : "=l"(v) : "f"(lo), "f"(hi)); return v;
}
__device__ __forceinline__ float ex2f(float x) {
    float r; asm("ex2.approx.f32 %0, %1;" : "=f"(r) : "f"(x)); return r;
}
__device__ __forceinline__ float rcpf(float x) {
    float r; asm("rcp.approx.f32 %0, %1;" : "=f"(r) : "f"(x)); return r;
}
// tanh(x) = 2/(1+e^{-2x}) - 1, via EX2 + RCP (no divergence, ~1e-6 err)
__device__ __forceinline__ float tanh_fast(float x) {
    return fmaf(rcpf(1.0f + ex2f(x * -2.8853900817779268f)), 2.0f, -1.0f);
}

// ---------------------------------------------------------------------------
// Kernel 0: one-time weight transposes for coalesced head GEMVs
// ---------------------------------------------------------------------------
__global__ void transpose_kernel(const float* __restrict__ Wg,
                                 const float* __restrict__ Wm,
                                 const float* __restrict__ Ws)
{
    int i = blockIdx.x * 256 + threadIdx.x;
    if (i < GATES * HID) {
        int j = i >> 6, k = i & 63;
        g_Wg_t[k * GATES + j] = Wg[i];
        int a = i >> 8, jj = i & 255;
        g_Wm_t[jj * HID + a] = Wm[i];
        g_Ws_t[jj * HID + a] = Ws[i];
    }
}

// ---------------------------------------------------------------------------
// Kernel 1: 64 independent LSTMs, one CTA per node, T=4096 steps.
// Thread tid -> (k = tid>>2, gate = tid&3). Row r = gate*64 + k.
// Branch-free activation: weights/bias pre-scaled by gate-specific -log2e
// multiplier so each step's activation is just EX2 -> RCP -> FMA.
// ---------------------------------------------------------------------------
__global__ void __launch_bounds__(256, 1)
lstm_kernel(const float* __restrict__ x,
            const float* __restrict__ W_ih,
            const float* __restrict__ W_hh,
            const float* __restrict__ b_ih,
            const float* __restrict__ b_hh,
            float* __restrict__ out)
{
    const int n    = blockIdx.x;
    const int tid  = threadIdx.x;
    const int k    = tid >> 2;
    const int gate = tid & 3;
    const int r    = gate * HID + k;
    const unsigned lane = tid & 31u;
    const unsigned lb   = lane & ~3u;

    // gate g (index 2) uses tanh = 2*sigm(2x)-1; others plain sigmoid.
    const bool  is_g = (gate == 2);
    const float m    = is_g ? -2.8853900817779268f : -1.4426950408889634f;
    const float Aact = is_g ?  2.0f : 1.0f;
    const float Bact = is_g ? -1.0f : 0.0f;

    __shared__ __align__(16) float h2[2][HID];
    __shared__ __align__(16) float xs[2][32][FPL];

    // weights in registers, PRE-SCALED by m, packed as f32x2
    ull whh[32];
    {
        const float* wrow = W_hh + r * HID;
#pragma unroll
        for (int i = 0; i < 32; i++)
            whh[i] = pack2(wrow[2*i] * m, wrow[2*i+1] * m);
    }
    ull wih[4];
    {
        const float* wrow = W_ih + r * FPL;
#pragma unroll
        for (int i = 0; i < 4; i++)
            wih[i] = pack2(wrow[2*i] * m, wrow[2*i+1] * m);
    }
    const float bsum = (b_ih[r] + b_hh[r]) * m;

    float c_reg = 0.0f;
    if (tid < HID) h2[0][tid] = 0.0f;

    // prologue: batch 0 of x
    {
        int s = tid >> 3, j = tid & 7;
        xs[0][s][j] = x[s * OBS_DIM + n * FPL + j];
    }
    __syncthreads();

    for (int b = 0; b < T_SEQ / 32; b++) {
        // prefetch next batch into a register (latency hidden over 32 steps)
        float xpref = 0.0f;
        {
            int tn = (b + 1) * 32 + (tid >> 3);
            if (tn < T_SEQ) xpref = x[tn * OBS_DIM + (n * FPL) + (tid & 7)];
        }
#pragma unroll 4
        for (int s = 0; s < 32; s++) {
            const int t   = b * 32 + s;
            const int par = s & 1;

            // acc = m * (bias + W_ih·x + W_hh·h)   (packed f32x2, 4 accums)
            ull a0 = pack2(bsum, 0.0f), a1 = 0, a2 = 0, a3 = 0;
            {
                const ulonglong2* xp = (const ulonglong2*)xs[b & 1][s];
                ulonglong2 xv0 = xp[0], xv1 = xp[1];
                ffma2(a0, wih[0], xv0.x);
                ffma2(a1, wih[1], xv0.y);
                ffma2(a2, wih[2], xv1.x);
                ffma2(a3, wih[3], xv1.y);
            }
            const ulonglong2* hp = (const ulonglong2*)h2[par];
#pragma unroll
            for (int mm = 0; mm < 8; mm++) {
                ulonglong2 hv0 = hp[2*mm], hv1 = hp[2*mm+1];
                ffma2(a0, whh[4*mm+0], hv0.x);
                ffma2(a1, whh[4*mm+1], hv0.y);
                ffma2(a2, whh[4*mm+2], hv1.x);
                ffma2(a3, whh[4*mm+3], hv1.y);
            }
            float2 f0 = unpack2(a0), f1 = unpack2(a1), f2 = unpack2(a2), f3 = unpack2(a3);
            float accv = ((f0.x + f0.y) + (f1.x + f1.y)) +
                         ((f2.x + f2.y) + (f3.x + f3.y));

            // branch-free activation: v = A * RCP(1 + EX2(acc)) + B
            float v = fmaf(rcpf(1.0f + ex2f(accv)), Aact, Bact);

            // gather i,f,g,o within warp (lanes lb..lb+3 share k)
            float vi = __shfl_sync(FULLMASK, v, lb);
            float vf = __shfl_sync(FULLMASK, v, lb | 1);
            float vg = __shfl_sync(FULLMASK, v, lb | 2);
            float vo = __shfl_sync(FULLMASK, v, lb | 3);

            if (gate == 0) {
                c_reg = vf * c_reg + vi * vg;
                float h = vo * tanh_fast(c_reg);
                h2[par ^ 1][k] = h;
                g_hs[(t * NNODES + n) * HID + k] = h;
            }
            // stage next x batch mid-way (write-only buffer this batch)
            if (s == 20) xs[(b + 1) & 1][tid >> 3][tid & 7] = xpref;
            __syncthreads();
        }
    }

    // hn / cn
    if (gate == 0) {
        const int base = 2 * T_SEQ * NNODES;
        out[base + n * HID + k] = h2[0][k];
        out[base + NNODES * HID + n * HID + k] = c_reg;
    }
}

// ---------------------------------------------------------------------------
// Kernel 2: fused mean-pool + head. 64 CTAs x 64 timesteps each.
// GAT collapses to identity-attention + mean-pool commutes with W_gat.
// ---------------------------------------------------------------------------
__global__ void __launch_bounds__(256, 1)
head_kernel(const float* __restrict__ b_gat,
            const float* __restrict__ b_mean,
            const float* __restrict__ b_std,
            float* __restrict__ out)
{
    const int t0  = blockIdx.x * 64;
    const int tid = threadIdx.x;

    __shared__ __align__(16) float hbar_s[64][HID];
    __shared__ float g_s[GATES];

    {
        const int k = tid & 63, q = tid >> 6;
#pragma unroll
        for (int i = 0; i < 16; i++) {
            const int tl = q + 4 * i;
            const float* base = g_hs + ((long)(t0 + tl) * NNODES) * HID + k;
            float s = 0.0f;
#pragma unroll 8
            for (int nn = 0; nn < NNODES; nn++) s += base[nn * HID];
            hbar_s[tl][k] = s * (1.0f / 64.0f);
        }
    }
    __syncthreads();

    const float bg = b_gat[tid];
    for (int i = 0; i < 64; i++) {
        const int t = t0 + i;
        {
            float acc = bg;
            const float* hb = hbar_s[i];
#pragma unroll
            for (int k = 0; k < HID; k++) acc += g_Wg_t[k * GATES + tid] * hb[k];
            g_s[tid] = fmaxf(acc, 0.0f);
        }
        __syncthreads();

        if (tid < 128) {
            const int  a      = tid & 63;
            const bool is_std = (tid >= 64);
            const float* Wt = is_std ? g_Ws_t : g_Wm_t;
            float acc = is_std ? b_std[a] : b_mean[a];
#pragma unroll 8
            for (int j = 0; j < GATES; j++) acc += Wt[j * HID + a] * g_s[j];
            if (is_std) {
                float sp = (acc > 20.0f) ? acc : log1pf(__expf(acc));
                sp = fminf(fmaxf(sp, 0.001f), 10.0f);
                out[T_SEQ * NNODES + t * NNODES + a] = sp;
            } else {
                out[t * NNODES + a] = acc;
            }
        }
        __syncthreads();
    }
}

// ---------------------------------------------------------------------------
// launch
// ---------------------------------------------------------------------------
extern "C" void kernel_launch(void* const* d_in, const int* in_sizes, int n_in,
                              void* d_out, int out_size)
{
    const float* x      = (const float*)d_in[0];
    const float* W_ih   = (const float*)d_in[1];
    const float* W_hh   = (const float*)d_in[2];
    const float* b_ih   = (const float*)d_in[3];
    const float* b_hh   = (const float*)d_in[4];
    const float* W_gat  = (const float*)d_in[5];
    // d_in[6], d_in[7] (att_src/att_dst) provably unused: identity adjacency
    // -> softmax over a single unmasked element == 1 for any logits.
    const float* b_gat  = (const float*)d_in[8];
    const float* W_mean = (const float*)d_in[9];
    const float* b_mean = (const float*)d_in[10];
    const float* W_std  = (const float*)d_in[11];
    const float* b_std  = (const float*)d_in[12];
    float* out = (float*)d_out;

    transpose_kernel<<<64, 256>>>(W_gat, W_mean, W_std);
    lstm_kernel<<<NNODES, 256>>>(x, W_ih, W_hh, b_ih, b_hh, out);
    head_kernel<<<T_SEQ / 64, 256>>>(b_gat, b_mean, b_std, out);
}